// round 2
// baseline (speedup 1.0000x reference)
#include <cuda_runtime.h>
#include <math.h>

#define B 16
#define T (1 << 20)
#define NTH 256
#define PER_TH 16
#define CHUNK (NTH * PER_TH)      // 4096
#define NCH (T / CHUNK)           // 256 chunks per row
#define STEP (1.0f / 48000.0f)
#define RISE_RATIO 0.66f
#define EPSV 1e-6f
#define PI_F 3.14159265358979f
#define FULL 0xFFFFFFFFu

// decoupled-lookback state (no device-side allocation allowed)
__device__ double g_agg[B * NCH];    // per-chunk aggregate (sum of f0*STEP)
__device__ double g_incl[B * NCH];   // inclusive prefix across chunks
__device__ int    g_flag[B * NCH];   // 0 = invalid, 1 = agg ready, 2 = incl ready

// ---------------- init: zero flags (must run every launch; graph replays) ----
__global__ void k_init() {
    int i = blockIdx.x * blockDim.x + threadIdx.x;
    if (i < B * NCH) g_flag[i] = 0;
}

// ---------------- single-pass scan + Rosenberg pulse -------------------------
__global__ __launch_bounds__(NTH) void k_scan(const float* __restrict__ f0,
                                              const float* __restrict__ oq,
                                              const float* __restrict__ ps,
                                              float* __restrict__ out,
                                              int out_size) {
    const int b = blockIdx.y, ch = blockIdx.x;
    const int idx = b * NCH + ch;
    const size_t base = (size_t)b * T + (size_t)ch * CHUNK;
    const int lane = threadIdx.x & 31, wid = threadIdx.x >> 5;

    const float4* pf = reinterpret_cast<const float4*>(f0 + base) + threadIdx.x * (PER_TH / 4);
    const float4* po = reinterpret_cast<const float4*>(oq + base) + threadIdx.x * (PER_TH / 4);
    float4*       pw = reinterpret_cast<float4*>(out + base)       + threadIdx.x * (PER_TH / 4);

    // Load f0 + oq (streaming), thread-local inclusive prefix of phase_step.
    // oq loads issued early so they are in flight during the lookback wait.
    float4 q[PER_TH / 4];
    float  s[PER_TH];
    float  acc = 0.f;
#pragma unroll
    for (int i = 0; i < PER_TH / 4; i++) {
        float4 v = __ldcs(&pf[i]);
        q[i] = __ldcs(&po[i]);
        acc += v.x * STEP; s[i * 4 + 0] = acc;
        acc += v.y * STEP; s[i * 4 + 1] = acc;
        acc += v.z * STEP; s[i * 4 + 2] = acc;
        acc += v.w * STEP; s[i * 4 + 3] = acc;
    }

    // warp inclusive scan of thread totals
    const float tot = acc;
    float incl = tot;
#pragma unroll
    for (int d = 1; d < 32; d <<= 1) {
        float n = __shfl_up_sync(FULL, incl, d);
        if (lane >= d) incl += n;
    }
    const float wexcl = incl - tot;

    __shared__ float  wsum[NTH / 32];
    __shared__ float  wbase[NTH / 32];
    __shared__ double s_excl;
    if (lane == 31) wsum[wid] = incl;
    __syncthreads();

    double agg_d = 0.0;            // valid on thread 0 only
    if (threadIdx.x == 0) {
        float r = 0.f;
#pragma unroll
        for (int i = 0; i < NTH / 32; i++) { wbase[i] = r; r += wsum[i]; }
        agg_d = (double)r;
        // publish aggregate ASAP so successors can make progress
        if (ch == 0) {
            g_incl[idx] = agg_d;
            __threadfence();
            ((volatile int*)g_flag)[idx] = 2;
            s_excl = 0.0;
        } else {
            g_agg[idx] = agg_d;
            __threadfence();
            ((volatile int*)g_flag)[idx] = 1;
        }
    }

    // warp-parallel decoupled lookback (warp 0 only)
    if (wid == 0 && ch > 0) {
        double excl = 0.0;
        int look = ch - 1;                       // highest chunk to inspect
        for (;;) {
            const int i  = look - 31 + lane;     // lane 31 reads 'look'
            const int gi = b * NCH + i;
            int f = 2;                           // i < 0 acts as inclusive=0
            if (i >= 0) f = ((volatile int*)g_flag)[gi];
            while (!__all_sync(FULL, f != 0)) {
                if (i >= 0) f = ((volatile int*)g_flag)[gi];
            }
            __threadfence();
            double val = 0.0;
            if (i >= 0)
                val = (f == 2) ? ((volatile double*)g_incl)[gi]
                               : ((volatile double*)g_agg)[gi];
            const unsigned has2 = __ballot_sync(FULL, (i < 0) || (f == 2));
            if (has2) {
                const int pivot = 31 - __clz(has2);      // highest inclusive lane
                double contrib = (lane >= pivot) ? val : 0.0;
#pragma unroll
                for (int d = 16; d; d >>= 1) contrib += __shfl_down_sync(FULL, contrib, d);
                if (lane == 0) excl += contrib;
                break;
            } else {
                double contrib = val;
#pragma unroll
                for (int d = 16; d; d >>= 1) contrib += __shfl_down_sync(FULL, contrib, d);
                if (lane == 0) excl += contrib;
                look -= 32;
            }
        }
        if (lane == 0) {
            s_excl = excl;
            g_incl[idx] = excl + agg_d;
            __threadfence();
            ((volatile int*)g_flag)[idx] = 2;
            if (ch == NCH - 1) {                  // next_state (unwrapped)
                const long long oi = (long long)B * T + b;
                if (oi < (long long)out_size)
                    out[oi] = (float)((double)ps[b] + excl + agg_d);
            }
        }
    }
    __syncthreads();

    // absolute phase base for this thread (fp64 only here)
    const double based = (double)ps[b] + s_excl + (double)(wbase[wid] + wexcl);
    const float frac = (float)(based - floor(based));    // in [0, 1]

#pragma unroll
    for (int i = 0; i < PER_TH / 4; i++) {
        float4 w;
        const float* qv = &q[i].x;
        float* wv = &w.x;
#pragma unroll
        for (int j = 0; j < 4; j++) {
            float ph = frac + s[i * 4 + j];
            ph -= floorf(ph);                    // wrapped to [0,1)
            const float oqv = qv[j];
            const float tp = oqv * RISE_RATIO;
            const float tn = oqv - tp;
            const bool rise = ph < tp;
            const bool open = ph < oqv;
            const float arg = rise ? __fdividef(PI_F * ph, tp + EPSV)
                                   : __fdividef(PI_F * (ph - tp), 2.f * tn + EPSV);
            const float c = __cosf(arg);
            wv[j] = rise ? 0.5f - 0.5f * c : (open ? c : 0.f);
        }
        __stcs(&pw[i], w);
    }
}

extern "C" void kernel_launch(void* const* d_in, const int* in_sizes, int n_in,
                              void* d_out, int out_size) {
    const float* f0 = (const float*)d_in[0];
    const float* oq = (const float*)d_in[1];
    const float* ps = (const float*)d_in[2];
    float* out = (float*)d_out;

    k_init<<<(B * NCH + 255) / 256, 256>>>();
    dim3 grid(NCH, B);
    k_scan<<<grid, NTH>>>(f0, oq, ps, out, out_size);
}

// round 3
// speedup vs baseline: 2.3253x; 2.3253x over previous
#include <cuda_runtime.h>
#include <math.h>

#define B 16
#define T (1 << 20)
#define NTH 256
#define PER 8
#define CHUNK (NTH * PER)         // 2048
#define NCH (T / CHUNK)           // 512 chunks per row
#define STEP (1.0f / 48000.0f)
#define RISE_RATIO 0.66f
#define EPSV 1e-6f
#define PI_F 3.14159265358979f
#define FULL 0xFFFFFFFFu

// scratch (no device-side allocation allowed)
__device__ float  g_partials[B * NCH];   // per-chunk sum of f0*STEP
__device__ double g_offsets[B * NCH];    // ps[b] + exclusive prefix across chunks

// ---------------- Pass 1: per-chunk sums (also warms L2 with f0) -------------
__global__ __launch_bounds__(NTH) void k_partials(const float* __restrict__ f0) {
    const int b = blockIdx.y, ch = blockIdx.x;
    const float4* p = reinterpret_cast<const float4*>(f0 + (size_t)b * T + (size_t)ch * CHUNK)
                      + threadIdx.x * (PER / 4);
    float s = 0.f;
#pragma unroll
    for (int i = 0; i < PER / 4; i++) {
        float4 v = p[i];                       // default caching: keep in L2
        s += (v.x + v.y) + (v.z + v.w);
    }
#pragma unroll
    for (int d = 16; d; d >>= 1) s += __shfl_down_sync(FULL, s, d);
    __shared__ float ws[NTH / 32];
    if ((threadIdx.x & 31) == 0) ws[threadIdx.x >> 5] = s;
    __syncthreads();
    if (threadIdx.x == 0) {
        float t = 0.f;
#pragma unroll
        for (int i = 0; i < NTH / 32; i++) t += ws[i];
        g_partials[b * NCH + ch] = t * STEP;
    }
}

// ---------------- Pass 2: parallel fp64 scan of chunk sums (1 block/row) -----
__global__ __launch_bounds__(NCH) void k_rowscan(const float* __restrict__ phase_state,
                                                 float* __restrict__ out, int out_size) {
    const int b = blockIdx.x;
    const int tid = threadIdx.x;               // == chunk index
    const int lane = tid & 31, wid = tid >> 5; // 16 warps
    const double v = (double)g_partials[b * NCH + tid];

    // warp inclusive scan (double)
    double incl = v;
#pragma unroll
    for (int d = 1; d < 32; d <<= 1) {
        double n = __shfl_up_sync(FULL, incl, d);
        if (lane >= d) incl += n;
    }
    __shared__ double wsum[NCH / 32];
    __shared__ double wbase[NCH / 32];
    if (lane == 31) wsum[wid] = incl;
    __syncthreads();
    if (tid == 0) {
        double r = 0.0;
#pragma unroll
        for (int i = 0; i < NCH / 32; i++) { wbase[i] = r; r += wsum[i]; }
    }
    __syncthreads();

    const double base = (double)phase_state[b];
    const double excl = base + wbase[wid] + (incl - v);
    g_offsets[b * NCH + tid] = excl;

    if (tid == NCH - 1) {                       // next_state (unwrapped)
        const long long oi = (long long)B * T + b;
        if (oi < (long long)out_size) out[oi] = (float)(excl + v);
    }
}

// ---------------- Pass 3: in-block scan + Rosenberg pulse --------------------
__global__ __launch_bounds__(NTH) void k_wav(const float* __restrict__ f0,
                                             const float* __restrict__ oq,
                                             float* __restrict__ out) {
    const int b = blockIdx.y, ch = blockIdx.x;
    const size_t base = (size_t)b * T + (size_t)ch * CHUNK;
    const int lane = threadIdx.x & 31, wid = threadIdx.x >> 5;

    const float4* pf = reinterpret_cast<const float4*>(f0 + base) + threadIdx.x * (PER / 4);
    const float4* po = reinterpret_cast<const float4*>(oq + base) + threadIdx.x * (PER / 4);
    float4*       pw = reinterpret_cast<float4*>(out + base)       + threadIdx.x * (PER / 4);

    // f0: default load (expect L2 hit, warmed by pass 1); oq: streaming.
    float4 q[PER / 4];
    float  s[PER];
    float  acc = 0.f;
#pragma unroll
    for (int i = 0; i < PER / 4; i++) {
        float4 v = pf[i];
        q[i] = __ldcs(&po[i]);
        acc += v.x * STEP; s[i * 4 + 0] = acc;
        acc += v.y * STEP; s[i * 4 + 1] = acc;
        acc += v.z * STEP; s[i * 4 + 2] = acc;
        acc += v.w * STEP; s[i * 4 + 3] = acc;
    }

    // block exclusive scan of thread totals (fp32; chunk sum < 0.05)
    const float tot = acc;
    float incl = tot;
#pragma unroll
    for (int d = 1; d < 32; d <<= 1) {
        float n = __shfl_up_sync(FULL, incl, d);
        if (lane >= d) incl += n;
    }
    const float wexcl = incl - tot;
    __shared__ float wsum[NTH / 32];
    __shared__ float wbase[NTH / 32];
    if (lane == 31) wsum[wid] = incl;
    __syncthreads();
    if (threadIdx.x == 0) {
        float r = 0.f;
#pragma unroll
        for (int i = 0; i < NTH / 32; i++) { wbase[i] = r; r += wsum[i]; }
    }
    __syncthreads();

    // absolute phase base for this thread (fp64 only here)
    const double based = g_offsets[b * NCH + ch] + (double)(wbase[wid] + wexcl);
    const float frac = (float)(based - floor(based));     // in [0, 1]

#pragma unroll
    for (int i = 0; i < PER / 4; i++) {
        float4 w;
        const float* qv = &q[i].x;
        float* wv = &w.x;
#pragma unroll
        for (int j = 0; j < 4; j++) {
            float ph = frac + s[i * 4 + j];
            ph -= floorf(ph);                  // wrapped to [0,1)
            const float oqv = qv[j];
            const float tp = oqv * RISE_RATIO;
            const float tn = oqv - tp;
            const bool rise = ph < tp;
            const bool open = ph < oqv;
            const float arg = rise ? __fdividef(PI_F * ph, tp + EPSV)
                                   : __fdividef(PI_F * (ph - tp), 2.f * tn + EPSV);
            const float c = __cosf(arg);
            wv[j] = rise ? 0.5f - 0.5f * c : (open ? c : 0.f);
        }
        __stcs(&pw[i], w);
    }
}

extern "C" void kernel_launch(void* const* d_in, const int* in_sizes, int n_in,
                              void* d_out, int out_size) {
    const float* f0 = (const float*)d_in[0];
    const float* oq = (const float*)d_in[1];
    const float* ps = (const float*)d_in[2];
    float* out = (float*)d_out;

    dim3 grid(NCH, B);
    k_partials<<<grid, NTH>>>(f0);
    k_rowscan<<<B, NCH>>>(ps, out, out_size);
    k_wav<<<grid, NTH>>>(f0, oq, out);
}

// round 4
// speedup vs baseline: 2.3362x; 1.0047x over previous
#include <cuda_runtime.h>
#include <math.h>

#define B 16
#define T (1 << 20)
#define NTH 256
#define PER 8
#define CHUNK (NTH * PER)         // 2048
#define NCH (T / CHUNK)           // 512 chunks per row
#define CPB 4                     // chunks per pass-1 block
#define CHUNK1 (CHUNK * CPB)      // 8192
#define STEP (1.0f / 48000.0f)
#define RISE_RATIO 0.66f
#define EPSV 1e-6f
#define PI_F 3.14159265358979f
#define FULL 0xFFFFFFFFu

// scratch (no device-side allocation allowed)
__device__ float  g_partials[B * NCH];   // per-chunk sum of f0*STEP
__device__ double g_offsets[B * NCH];    // ps[b] + exclusive prefix across chunks

// ------- Pass 1: per-chunk sums, 4 chunks/block, loads batched up front ------
__global__ __launch_bounds__(NTH) void k_partials(const float* __restrict__ f0) {
    const int b = blockIdx.y, cg = blockIdx.x;
    const float4* p = reinterpret_cast<const float4*>(f0 + (size_t)b * T + (size_t)cg * CHUNK1);
    const int t = threadIdx.x;

    // 8 fully-coalesced LDG.128 issued back-to-back (high MLP_p1)
    float4 v[2 * CPB];
#pragma unroll
    for (int c = 0; c < CPB; c++) {
        v[2 * c + 0] = p[c * 512 + t];          // each chunk = 512 float4
        v[2 * c + 1] = p[c * 512 + 256 + t];
    }

    float s[CPB];
#pragma unroll
    for (int c = 0; c < CPB; c++) {
        const float4 a = v[2 * c], d = v[2 * c + 1];
        s[c] = ((a.x + a.y) + (a.z + a.w)) + ((d.x + d.y) + (d.z + d.w));
    }

    // four independent warp reductions (pipelined)
#pragma unroll
    for (int d = 16; d; d >>= 1) {
#pragma unroll
        for (int c = 0; c < CPB; c++) s[c] += __shfl_down_sync(FULL, s[c], d);
    }
    __shared__ float ws[CPB][NTH / 32];
    if ((t & 31) == 0) {
        const int w = t >> 5;
#pragma unroll
        for (int c = 0; c < CPB; c++) ws[c][w] = s[c];
    }
    __syncthreads();
    if (t < CPB) {
        float r = 0.f;
#pragma unroll
        for (int i = 0; i < NTH / 32; i++) r += ws[t][i];
        g_partials[b * NCH + cg * CPB + t] = r * STEP;
    }
}

// ---------------- Pass 2: parallel fp64 scan of chunk sums (1 block/row) -----
__global__ __launch_bounds__(NCH) void k_rowscan(const float* __restrict__ phase_state,
                                                 float* __restrict__ out, int out_size) {
    const int b = blockIdx.x;
    const int tid = threadIdx.x;               // == chunk index
    const int lane = tid & 31, wid = tid >> 5; // 16 warps
    const double v = (double)g_partials[b * NCH + tid];

    double incl = v;
#pragma unroll
    for (int d = 1; d < 32; d <<= 1) {
        double n = __shfl_up_sync(FULL, incl, d);
        if (lane >= d) incl += n;
    }
    __shared__ double wsum[NCH / 32];
    __shared__ double wbase[NCH / 32];
    if (lane == 31) wsum[wid] = incl;
    __syncthreads();
    if (tid == 0) {
        double r = 0.0;
#pragma unroll
        for (int i = 0; i < NCH / 32; i++) { wbase[i] = r; r += wsum[i]; }
    }
    __syncthreads();

    const double excl = (double)phase_state[b] + wbase[wid] + (incl - v);
    g_offsets[b * NCH + tid] = excl;

    if (tid == NCH - 1) {                       // next_state (unwrapped)
        const long long oi = (long long)B * T + b;
        if (oi < (long long)out_size) out[oi] = (float)(excl + v);
    }
}

// ---------------- Pass 3: in-block scan + Rosenberg pulse --------------------
__global__ __launch_bounds__(NTH) void k_wav(const float* __restrict__ f0,
                                             const float* __restrict__ oq,
                                             float* __restrict__ out) {
    const int b = blockIdx.y, ch = blockIdx.x;
    const size_t base = (size_t)b * T + (size_t)ch * CHUNK;
    const int lane = threadIdx.x & 31, wid = threadIdx.x >> 5;

    const float4* pf = reinterpret_cast<const float4*>(f0 + base) + threadIdx.x * (PER / 4);
    const float4* po = reinterpret_cast<const float4*>(oq + base) + threadIdx.x * (PER / 4);
    float4*       pw = reinterpret_cast<float4*>(out + base)       + threadIdx.x * (PER / 4);

    // f0: default load (L2 hit, warmed by pass 1); oq: streaming.
    float4 q[PER / 4];
    float  s[PER];
    float  acc = 0.f;
#pragma unroll
    for (int i = 0; i < PER / 4; i++) {
        float4 v = pf[i];
        q[i] = __ldcs(&po[i]);
        acc += v.x * STEP; s[i * 4 + 0] = acc;
        acc += v.y * STEP; s[i * 4 + 1] = acc;
        acc += v.z * STEP; s[i * 4 + 2] = acc;
        acc += v.w * STEP; s[i * 4 + 3] = acc;
    }

    // block exclusive scan of thread totals (fp32; chunk sum tiny)
    const float tot = acc;
    float incl = tot;
#pragma unroll
    for (int d = 1; d < 32; d <<= 1) {
        float n = __shfl_up_sync(FULL, incl, d);
        if (lane >= d) incl += n;
    }
    const float wexcl = incl - tot;
    __shared__ float wsum[NTH / 32];
    __shared__ float wbase[NTH / 32];
    if (lane == 31) wsum[wid] = incl;
    __syncthreads();
    if (threadIdx.x == 0) {
        float r = 0.f;
#pragma unroll
        for (int i = 0; i < NTH / 32; i++) { wbase[i] = r; r += wsum[i]; }
    }
    __syncthreads();

    // absolute phase base for this thread (fp64 only here)
    const double based = g_offsets[b * NCH + ch] + (double)(wbase[wid] + wexcl);
    const float frac = (float)(based - floor(based));     // in [0, 1]

#pragma unroll
    for (int i = 0; i < PER / 4; i++) {
        float4 w;
        const float* qv = &q[i].x;
        float* wv = &w.x;
#pragma unroll
        for (int j = 0; j < 4; j++) {
            float ph = frac + s[i * 4 + j];
            ph -= floorf(ph);                  // wrapped to [0,1)
            const float oqv = qv[j];
            const float tp = oqv * RISE_RATIO;
            const float tn = oqv - tp;
            const bool rise = ph < tp;
            const bool open = ph < oqv;
            const float arg = rise ? __fdividef(PI_F * ph, tp + EPSV)
                                   : __fdividef(PI_F * (ph - tp), 2.f * tn + EPSV);
            const float c = __cosf(arg);
            wv[j] = rise ? 0.5f - 0.5f * c : (open ? c : 0.f);
        }
        __stcs(&pw[i], w);
    }
}

extern "C" void kernel_launch(void* const* d_in, const int* in_sizes, int n_in,
                              void* d_out, int out_size) {
    const float* f0 = (const float*)d_in[0];
    const float* oq = (const float*)d_in[1];
    const float* ps = (const float*)d_in[2];
    float* out = (float*)d_out;

    dim3 grid1(NCH / CPB, B);
    k_partials<<<grid1, NTH>>>(f0);
    k_rowscan<<<B, NCH>>>(ps, out, out_size);
    dim3 grid3(NCH, B);
    k_wav<<<grid3, NTH>>>(f0, oq, out);
}

// round 5
// speedup vs baseline: 2.5210x; 1.0791x over previous
#include <cuda_runtime.h>
#include <math.h>

#define B 16
#define T (1 << 20)
#define NTH 256
#define PER 8
#define CHUNK (NTH * PER)         // 2048
#define NCH (T / CHUNK)           // 512 chunks per row
#define CPB 8                     // chunks per pass-1 block
#define CHUNK1 (CHUNK * CPB)      // 16384 elems per pass-1 block
#define BPR (NCH / CPB)           // 64 pass-1 blocks per row
#define STEP (1.0f / 48000.0f)
#define RISE_RATIO 0.66f
#define EPSV 1e-6f
#define PI_F 3.14159265358979f
#define FULL 0xFFFFFFFFu

// scratch (no device-side allocation allowed)
__device__ float  g_partials[B * NCH];   // per-chunk sum of f0*STEP
__device__ double g_offsets[B * NCH];    // ps[b] + exclusive prefix across chunks
__device__ int    g_count[B];            // per-row completion counters (self-resetting)

// ------- Pass 1: per-chunk sums; last block per row also scans the row -------
__global__ __launch_bounds__(NTH) void k_partials(const float* __restrict__ f0,
                                                  const float* __restrict__ ps,
                                                  float* __restrict__ out,
                                                  int out_size) {
    const int b = blockIdx.y, cg = blockIdx.x;
    const float4* p = reinterpret_cast<const float4*>(f0 + (size_t)b * T + (size_t)cg * CHUNK1);
    const int t = threadIdx.x;
    const int lane = t & 31, wid = t >> 5;

    // 16 coalesced LDG.128 per thread, two front-batched groups of 8
    float s[CPB];
    {
        float4 v[CPB];
#pragma unroll
        for (int c = 0; c < CPB; c++) v[c] = p[c * 512 + t];
#pragma unroll
        for (int c = 0; c < CPB; c++)
            s[c] = (v[c].x + v[c].y) + (v[c].z + v[c].w);
#pragma unroll
        for (int c = 0; c < CPB; c++) v[c] = p[c * 512 + 256 + t];
#pragma unroll
        for (int c = 0; c < CPB; c++)
            s[c] += (v[c].x + v[c].y) + (v[c].z + v[c].w);
    }

    // CPB independent warp reductions
#pragma unroll
    for (int d = 16; d; d >>= 1) {
#pragma unroll
        for (int c = 0; c < CPB; c++) s[c] += __shfl_down_sync(FULL, s[c], d);
    }
    __shared__ float ws[CPB][NTH / 32];
    if (lane == 0) {
#pragma unroll
        for (int c = 0; c < CPB; c++) ws[c][wid] = s[c];
    }
    __syncthreads();
    if (t < CPB) {
        float r = 0.f;
#pragma unroll
        for (int i = 0; i < NTH / 32; i++) r += ws[t][i];
        g_partials[b * NCH + cg * CPB + t] = r * STEP;
    }

    // ---- last block of this row performs the fp64 row scan ----
    __shared__ int s_last;
    __syncthreads();
    if (t == 0) {
        __threadfence();                              // publish partials
        s_last = (atomicAdd(&g_count[b], 1) == BPR - 1);
    }
    __syncthreads();
    if (!s_last) return;
    __threadfence();                                  // see all rows' partials

    // 256 threads, 2 chunks each: scan 512 chunk sums in double
    const float* pr = g_partials + b * NCH;
    const double v0 = (double)pr[2 * t];
    const double v1 = (double)pr[2 * t + 1];
    const double pair = v0 + v1;

    double incl = pair;
#pragma unroll
    for (int d = 1; d < 32; d <<= 1) {
        double n = __shfl_up_sync(FULL, incl, d);
        if (lane >= d) incl += n;
    }
    __shared__ double dwsum[NTH / 32];
    __shared__ double dwbase[NTH / 32];
    if (lane == 31) dwsum[wid] = incl;
    __syncthreads();
    if (t == 0) {
        double r = 0.0;
#pragma unroll
        for (int i = 0; i < NTH / 32; i++) { dwbase[i] = r; r += dwsum[i]; }
        g_count[b] = 0;                               // reset for next graph replay
    }
    __syncthreads();

    const double excl = (double)ps[b] + dwbase[wid] + (incl - pair);
    g_offsets[b * NCH + 2 * t]     = excl;
    g_offsets[b * NCH + 2 * t + 1] = excl + v0;

    if (t == NTH - 1) {                               // next_state (unwrapped)
        const long long oi = (long long)B * T + b;
        if (oi < (long long)out_size) out[oi] = (float)(excl + pair);
    }
}

// ---------------- Pass 2: in-block scan + Rosenberg pulse --------------------
__global__ __launch_bounds__(NTH) void k_wav(const float* __restrict__ f0,
                                             const float* __restrict__ oq,
                                             float* __restrict__ out) {
    const int b = blockIdx.y, ch = blockIdx.x;
    const size_t base = (size_t)b * T + (size_t)ch * CHUNK;
    const int lane = threadIdx.x & 31, wid = threadIdx.x >> 5;

    const float4* pf = reinterpret_cast<const float4*>(f0 + base) + threadIdx.x * (PER / 4);
    const float4* po = reinterpret_cast<const float4*>(oq + base) + threadIdx.x * (PER / 4);
    float4*       pw = reinterpret_cast<float4*>(out + base)       + threadIdx.x * (PER / 4);

    // f0: default load (L2 hit, warmed by pass 1); oq: streaming.
    float4 q[PER / 4];
    float  s[PER];
    float  acc = 0.f;
#pragma unroll
    for (int i = 0; i < PER / 4; i++) {
        float4 v = pf[i];
        q[i] = __ldcs(&po[i]);
        acc += v.x * STEP; s[i * 4 + 0] = acc;
        acc += v.y * STEP; s[i * 4 + 1] = acc;
        acc += v.z * STEP; s[i * 4 + 2] = acc;
        acc += v.w * STEP; s[i * 4 + 3] = acc;
    }

    // block exclusive scan of thread totals (fp32; chunk sum tiny)
    const float tot = acc;
    float incl = tot;
#pragma unroll
    for (int d = 1; d < 32; d <<= 1) {
        float n = __shfl_up_sync(FULL, incl, d);
        if (lane >= d) incl += n;
    }
    const float wexcl = incl - tot;
    __shared__ float wsum[NTH / 32];
    __shared__ float wbase[NTH / 32];
    if (lane == 31) wsum[wid] = incl;
    __syncthreads();
    if (threadIdx.x == 0) {
        float r = 0.f;
#pragma unroll
        for (int i = 0; i < NTH / 32; i++) { wbase[i] = r; r += wsum[i]; }
    }
    __syncthreads();

    // absolute phase base for this thread (fp64 only here)
    const double based = g_offsets[b * NCH + ch] + (double)(wbase[wid] + wexcl);
    const float frac = (float)(based - floor(based));     // in [0, 1]

#pragma unroll
    for (int i = 0; i < PER / 4; i++) {
        float4 w;
        const float* qv = &q[i].x;
        float* wv = &w.x;
#pragma unroll
        for (int j = 0; j < 4; j++) {
            float ph = frac + s[i * 4 + j];
            ph -= floorf(ph);                  // wrapped to [0,1)
            const float oqv = qv[j];
            const float tp = oqv * RISE_RATIO;
            const float tn = oqv - tp;
            const bool rise = ph < tp;
            const bool open = ph < oqv;
            const float arg = rise ? __fdividef(PI_F * ph, tp + EPSV)
                                   : __fdividef(PI_F * (ph - tp), 2.f * tn + EPSV);
            const float c = __cosf(arg);
            wv[j] = rise ? 0.5f - 0.5f * c : (open ? c : 0.f);
        }
        __stcs(&pw[i], w);
    }
}

extern "C" void kernel_launch(void* const* d_in, const int* in_sizes, int n_in,
                              void* d_out, int out_size) {
    const float* f0 = (const float*)d_in[0];
    const float* oq = (const float*)d_in[1];
    const float* ps = (const float*)d_in[2];
    float* out = (float*)d_out;

    dim3 grid1(BPR, B);
    k_partials<<<grid1, NTH>>>(f0, ps, out, out_size);
    dim3 grid3(NCH, B);
    k_wav<<<grid3, NTH>>>(f0, oq, out);
}